// round 6
// baseline (speedup 1.0000x reference)
#include <cuda_runtime.h>
#include <math.h>

#define BATCH 256
#define LTOK  576
#define DDIM  1024
#define EPSV  1e-8f
#define TOK_PER_BLOCK 8
#define BLOCKS_PER_B  (LTOK / TOK_PER_BLOCK)   // 72
#define KMAX  64

// scratch
__device__ float g_sims[BATCH * LTOK];
__device__ int   g_cnt[BATCH];                 // zero-init; self-resetting

__device__ __forceinline__ unsigned long long pack_key(float v, int idx) {
    unsigned int u = __float_as_uint(v);
    u = (u & 0x80000000u) ? ~u : (u | 0x80000000u);   // monotonic float->uint
    return ((unsigned long long)u << 10) | (unsigned int)idx;
}

// ---------------------------------------------------------------------------
// Fused kernel: cosine sims stream (one warp/token, 8 tokens of one batch row
// per block) + last-arriving block per batch does bottom-k selection (warp 0,
// register keys, shfl-only) and the gather-mean epilogue for that batch.
// Epilogues overlap with the ongoing stream on other SMs; gather hits L2.
// ---------------------------------------------------------------------------
__global__ __launch_bounds__(256) void fused_kernel(
    const float* __restrict__ ifeat,   // [B, D]
    const float* __restrict__ img,     // [B, L, D]
    const int*   __restrict__ kptr,
    float*       __restrict__ out)     // [B, D]
{
    const int b    = blockIdx.x / BLOCKS_PER_B;
    const int tok0 = (blockIdx.x % BLOCKS_PER_B) * TOK_PER_BLOCK;
    const int warp = threadIdx.x >> 5;
    const int lane = threadIdx.x & 31;
    const int tid  = threadIdx.x;

    __shared__ float4 i_sm[DDIM / 4];          // 4 KB
    __shared__ int    s_idx[KMAX];
    __shared__ int    s_last;

    i_sm[tid] = ((const float4*)(ifeat + (size_t)b * DDIM))[tid];
    __syncthreads();

    // ---- sims for this block's 8 tokens ----
    const int l = tok0 + warp;
    const float4* trow = (const float4*)(img + ((size_t)b * LTOK + l) * DDIM);

    float dot = 0.f, nt = 0.f, ni = 0.f;
#pragma unroll
    for (int it = 0; it < 8; it++) {
        int idx = it * 32 + lane;
        float4 t  = trow[idx];
        float4 iv = i_sm[idx];
        dot = fmaf(t.x, iv.x, fmaf(t.y, iv.y, fmaf(t.z, iv.z, fmaf(t.w, iv.w, dot))));
        nt  = fmaf(t.x, t.x,  fmaf(t.y, t.y,  fmaf(t.z, t.z,  fmaf(t.w, t.w,  nt))));
        ni  = fmaf(iv.x, iv.x, fmaf(iv.y, iv.y, fmaf(iv.z, iv.z, fmaf(iv.w, iv.w, ni))));
    }
#pragma unroll
    for (int o = 16; o; o >>= 1) {
        dot += __shfl_xor_sync(0xFFFFFFFFu, dot, o);
        nt  += __shfl_xor_sync(0xFFFFFFFFu, nt,  o);
        ni  += __shfl_xor_sync(0xFFFFFFFFu, ni,  o);
    }
    if (lane == 0) {
        float denom = fmaxf(sqrtf(ni) * sqrtf(nt), EPSV);
        g_sims[b * LTOK + l] = dot / denom;
    }
    __syncthreads();

    // ---- arrive; last block of this batch runs the epilogue ----
    if (tid == 0) {
        __threadfence();                                       // publish sims
        s_last = (atomicAdd(&g_cnt[b], 1) == BLOCKS_PER_B - 1);
    }
    __syncthreads();
    if (!s_last) return;
    __threadfence();                                           // acquire sims

    int k = *kptr;
    if (k < 1) k = 1;
    if (k > KMAX) k = KMAX;

    // ---- bottom-k selection: warp 0 only, register keys, shfl reduce ----
    if (warp == 0) {
        unsigned long long keys[LTOK / 32];                    // 18 per lane
#pragma unroll
        for (int j = 0; j < LTOK / 32; j++) {
            int idx = j * 32 + lane;
            keys[j] = pack_key(g_sims[b * LTOK + idx], idx);
        }
        for (int r = 0; r < k; r++) {
            unsigned long long m = keys[0];
#pragma unroll
            for (int j = 1; j < LTOK / 32; j++) m = min(m, keys[j]);
#pragma unroll
            for (int o = 16; o; o >>= 1) {
                unsigned long long om = __shfl_xor_sync(0xFFFFFFFFu, m, o);
                m = min(m, om);
            }
            if (lane == 0) s_idx[r] = (int)(m & 1023u);
#pragma unroll
            for (int j = 0; j < LTOK / 32; j++)
                if (keys[j] == m) keys[j] = 0xFFFFFFFFFFFFFFFFull;
        }
    }
    __syncthreads();

    // ---- gather-mean: 256 threads, each owns one float4 column ----
    float4 acc = make_float4(0.f, 0.f, 0.f, 0.f);
#pragma unroll 4
    for (int j = 0; j < k; j++) {
        const float4* row = (const float4*)(img + ((size_t)b * LTOK + s_idx[j]) * DDIM);
        float4 t = __ldg(&row[tid]);
        acc.x += t.x; acc.y += t.y; acc.z += t.z; acc.w += t.w;
    }
    const float inv = 1.0f / (float)k;
    float4 r = make_float4(acc.x * inv, acc.y * inv, acc.z * inv, acc.w * inv);
    ((float4*)(out + (size_t)b * DDIM))[tid] = r;

    if (tid == 0) g_cnt[b] = 0;    // self-reset for next graph replay
}

extern "C" void kernel_launch(void* const* d_in, const int* in_sizes, int n_in,
                              void* d_out, int out_size)
{
    const float* i_feats = 0;
    const float* img     = 0;
    const int*   kptr    = 0;
    for (int i = 0; i < n_in; i++) {
        if (in_sizes[i] == BATCH * DDIM)             i_feats = (const float*)d_in[i];
        else if (in_sizes[i] == BATCH * LTOK * DDIM) img     = (const float*)d_in[i];
        else                                         kptr    = (const int*)d_in[i];
    }
    float* out = (float*)d_out;

    fused_kernel<<<BATCH * BLOCKS_PER_B, 256>>>(i_feats, img, kptr, out);
}

// round 7
// speedup vs baseline: 1.0528x; 1.0528x over previous
#include <cuda_runtime.h>
#include <math.h>

#define BATCH 256
#define LTOK  576
#define DDIM  1024
#define EPSV  1e-8f
#define TOK_PER_BLOCK 8
#define BLOCKS_PER_B  (LTOK / TOK_PER_BLOCK)   // 72
#define KMAX  64

// scratch
__device__ float g_sims[BATCH * LTOK];
__device__ int   g_cnt[BATCH];                 // zero-init; self-resetting

// ---------------------------------------------------------------------------
// Fused kernel: cosine-sim stream (one warp/token, 8 tokens of one batch row
// per block) + last-arriving block per batch runs the epilogue:
//   * bottom-k selection in SMEM by warp 0 (no register arrays, no barriers)
//   * gather-mean of the k selected rows (L2-resident) by all 256 threads.
// __launch_bounds__(256, 6) pins regs ~<=42 so the stream keeps 6 blocks/SM.
// ---------------------------------------------------------------------------
__global__ __launch_bounds__(256, 6) void fused_kernel(
    const float* __restrict__ ifeat,   // [B, D]
    const float* __restrict__ img,     // [B, L, D]
    const int*   __restrict__ kptr,
    float*       __restrict__ out)     // [B, D]
{
    const int b    = blockIdx.x / BLOCKS_PER_B;
    const int tok0 = (blockIdx.x % BLOCKS_PER_B) * TOK_PER_BLOCK;
    const int warp = threadIdx.x >> 5;
    const int lane = threadIdx.x & 31;
    const int tid  = threadIdx.x;

    __shared__ float4 i_sm[DDIM / 4];          // 4 KB
    __shared__ float  s_sims[LTOK];            // epilogue only
    __shared__ int    s_idx[KMAX];
    __shared__ int    s_last;

    i_sm[tid] = ((const float4*)(ifeat + (size_t)b * DDIM))[tid];
    __syncthreads();

    // ---- sims for this block's 8 tokens ----
    const int l = tok0 + warp;
    const float4* trow = (const float4*)(img + ((size_t)b * LTOK + l) * DDIM);

    float dot = 0.f, nt = 0.f, ni = 0.f;
#pragma unroll
    for (int it = 0; it < 8; it++) {
        int idx = it * 32 + lane;
        float4 t  = trow[idx];
        float4 iv = i_sm[idx];
        dot = fmaf(t.x, iv.x, fmaf(t.y, iv.y, fmaf(t.z, iv.z, fmaf(t.w, iv.w, dot))));
        nt  = fmaf(t.x, t.x,  fmaf(t.y, t.y,  fmaf(t.z, t.z,  fmaf(t.w, t.w,  nt))));
        ni  = fmaf(iv.x, iv.x, fmaf(iv.y, iv.y, fmaf(iv.z, iv.z, fmaf(iv.w, iv.w, ni))));
    }
#pragma unroll
    for (int o = 16; o; o >>= 1) {
        dot += __shfl_xor_sync(0xFFFFFFFFu, dot, o);
        nt  += __shfl_xor_sync(0xFFFFFFFFu, nt,  o);
        ni  += __shfl_xor_sync(0xFFFFFFFFu, ni,  o);
    }
    if (lane == 0) {
        float denom = fmaxf(sqrtf(ni) * sqrtf(nt), EPSV);
        g_sims[b * LTOK + l] = dot / denom;
    }
    __syncthreads();

    // ---- arrive; last block of this batch runs the epilogue ----
    if (tid == 0) {
        __threadfence();                                       // publish sims
        s_last = (atomicAdd(&g_cnt[b], 1) == BLOCKS_PER_B - 1);
    }
    __syncthreads();
    if (!s_last) return;
    __threadfence();                                           // acquire sims

    int k = *kptr;
    if (k < 1) k = 1;
    if (k > KMAX) k = KMAX;

    // stage sims into smem
    for (int i = tid; i < LTOK; i += 256)
        s_sims[i] = g_sims[b * LTOK + i];
    __syncthreads();

    // ---- bottom-k: warp 0, smem argmin, lowest-index tie-break ----
    if (warp == 0) {
        for (int r = 0; r < k; r++) {
            float bv = INFINITY; int bi = 0x7FFFFFFF;
#pragma unroll
            for (int j = 0; j < LTOK / 32; j++) {
                int i = j * 32 + lane;
                float v = s_sims[i];
                if (v < bv || (v == bv && i < bi)) { bv = v; bi = i; }
            }
#pragma unroll
            for (int o = 16; o; o >>= 1) {
                float ov = __shfl_xor_sync(0xFFFFFFFFu, bv, o);
                int   oi = __shfl_xor_sync(0xFFFFFFFFu, bi, o);
                if (ov < bv || (ov == bv && oi < bi)) { bv = ov; bi = oi; }
            }
            if (lane == 0) {
                s_idx[r] = bi;
                s_sims[bi] = INFINITY;     // remove winner
            }
            __syncwarp();
        }
    }
    __syncthreads();

    // ---- gather-mean: 256 threads, each owns one float4 column ----
    float4 acc = make_float4(0.f, 0.f, 0.f, 0.f);
#pragma unroll 4
    for (int j = 0; j < k; j++) {
        const float4* row = (const float4*)(img + ((size_t)b * LTOK + s_idx[j]) * DDIM);
        float4 t = __ldg(&row[tid]);
        acc.x += t.x; acc.y += t.y; acc.z += t.z; acc.w += t.w;
    }
    const float inv = 1.0f / (float)k;
    float4 r = make_float4(acc.x * inv, acc.y * inv, acc.z * inv, acc.w * inv);
    ((float4*)(out + (size_t)b * DDIM))[tid] = r;

    if (tid == 0) g_cnt[b] = 0;    // self-reset for next graph replay
}

extern "C" void kernel_launch(void* const* d_in, const int* in_sizes, int n_in,
                              void* d_out, int out_size)
{
    const float* i_feats = 0;
    const float* img     = 0;
    const int*   kptr    = 0;
    for (int i = 0; i < n_in; i++) {
        if (in_sizes[i] == BATCH * DDIM)             i_feats = (const float*)d_in[i];
        else if (in_sizes[i] == BATCH * LTOK * DDIM) img     = (const float*)d_in[i];
        else                                         kptr    = (const int*)d_in[i];
    }
    float* out = (float*)d_out;

    fused_kernel<<<BATCH * BLOCKS_PER_B, 256>>>(i_feats, img, kptr, out);
}

// round 8
// speedup vs baseline: 1.2085x; 1.1479x over previous
#include <cuda_runtime.h>
#include <math.h>

#define BATCH 256
#define LTOK  576
#define DDIM  1024
#define EPSV  1e-8f
#define TOK_PER_BLOCK 8
#define KMAX  64

// scratch: sims[B, L]
__device__ float g_sims[BATCH * LTOK];

// ---------------------------------------------------------------------------
// Kernel 1: cosine sims. One warp per token; 8 tokens (same batch row) per
// block so i_feats[b] is staged in smem once. Fully coalesced float4 streams.
// Measured 86.3us @ 7.06 TB/s (88.2% spec) — at roofline. DO NOT TOUCH.
// ---------------------------------------------------------------------------
__global__ __launch_bounds__(256) void sims_kernel(
    const float* __restrict__ ifeat,   // [B, D]
    const float* __restrict__ img)     // [B, L, D]
{
    const int blocks_per_b = LTOK / TOK_PER_BLOCK;        // 72
    const int b    = blockIdx.x / blocks_per_b;
    const int tok0 = (blockIdx.x % blocks_per_b) * TOK_PER_BLOCK;
    const int warp = threadIdx.x >> 5;
    const int lane = threadIdx.x & 31;

    __shared__ float4 i_sm[DDIM / 4];                     // 4 KB
    i_sm[threadIdx.x] = ((const float4*)(ifeat + (size_t)b * DDIM))[threadIdx.x];
    __syncthreads();

    const int l = tok0 + warp;
    const float4* trow = (const float4*)(img + ((size_t)b * LTOK + l) * DDIM);

    float dot = 0.f, nt = 0.f, ni = 0.f;
#pragma unroll
    for (int it = 0; it < 8; it++) {
        int idx = it * 32 + lane;
        float4 t  = trow[idx];
        float4 iv = i_sm[idx];
        dot = fmaf(t.x, iv.x, fmaf(t.y, iv.y, fmaf(t.z, iv.z, fmaf(t.w, iv.w, dot))));
        nt  = fmaf(t.x, t.x,  fmaf(t.y, t.y,  fmaf(t.z, t.z,  fmaf(t.w, t.w,  nt))));
        ni  = fmaf(iv.x, iv.x, fmaf(iv.y, iv.y, fmaf(iv.z, iv.z, fmaf(iv.w, iv.w, ni))));
    }
#pragma unroll
    for (int o = 16; o; o >>= 1) {
        dot += __shfl_xor_sync(0xFFFFFFFFu, dot, o);
        nt  += __shfl_xor_sync(0xFFFFFFFFu, nt,  o);
        ni  += __shfl_xor_sync(0xFFFFFFFFu, ni,  o);
    }
    if (lane == 0) {
        float denom = fmaxf(sqrtf(ni) * sqrtf(nt), EPSV);
        g_sims[b * LTOK + l] = dot / denom;
    }
}

// ---------------------------------------------------------------------------
// Kernel 2 (single tail kernel): per batch block —
//   warp 0: bottom-k via register-resident packed keys, shfl-only rounds
//           (min key == min sim, lowest-index tie-break = jax top_k semantics)
//   all 256 threads: gather-mean of the k selected rows, unroll-4 MLP.
// ---------------------------------------------------------------------------
__device__ __forceinline__ unsigned long long pack_key(float v, int idx) {
    unsigned int u = __float_as_uint(v);
    u = (u & 0x80000000u) ? ~u : (u | 0x80000000u);   // monotonic float->uint
    return ((unsigned long long)u << 10) | (unsigned int)idx;
}

__global__ __launch_bounds__(256) void tail_kernel(
    const float* __restrict__ img,     // [B, L, D]
    const int*   __restrict__ kptr,
    float*       __restrict__ out)     // [B, D]
{
    const int b    = blockIdx.x;
    const int tid  = threadIdx.x;
    const int warp = tid >> 5;
    const int lane = tid & 31;

    int k = *kptr;
    if (k < 1) k = 1;
    if (k > KMAX) k = KMAX;

    __shared__ int s_idx[KMAX];

    if (warp == 0) {
        unsigned long long keys[LTOK / 32];               // 18 per lane
#pragma unroll
        for (int j = 0; j < LTOK / 32; j++) {
            int idx = j * 32 + lane;
            keys[j] = pack_key(g_sims[b * LTOK + idx], idx);
        }
        for (int r = 0; r < k; r++) {
            unsigned long long m = keys[0];
#pragma unroll
            for (int j = 1; j < LTOK / 32; j++) m = min(m, keys[j]);
#pragma unroll
            for (int o = 16; o; o >>= 1) {
                unsigned long long om = __shfl_xor_sync(0xFFFFFFFFu, m, o);
                m = min(m, om);
            }
            if (lane == 0) s_idx[r] = (int)(m & 1023u);
#pragma unroll
            for (int j = 0; j < LTOK / 32; j++)
                if (keys[j] == m) keys[j] = 0xFFFFFFFFFFFFFFFFull;
        }
    }
    __syncthreads();

    // gather-mean: thread tid owns float4 column tid
    float4 acc = make_float4(0.f, 0.f, 0.f, 0.f);
#pragma unroll 4
    for (int j = 0; j < k; j++) {
        const float4* row = (const float4*)(img + ((size_t)b * LTOK + s_idx[j]) * DDIM);
        float4 t = __ldg(&row[tid]);
        acc.x += t.x; acc.y += t.y; acc.z += t.z; acc.w += t.w;
    }
    const float inv = 1.0f / (float)k;
    float4 r = make_float4(acc.x * inv, acc.y * inv, acc.z * inv, acc.w * inv);
    ((float4*)(out + (size_t)b * DDIM))[tid] = r;
}

extern "C" void kernel_launch(void* const* d_in, const int* in_sizes, int n_in,
                              void* d_out, int out_size)
{
    const float* i_feats = 0;
    const float* img     = 0;
    const int*   kptr    = 0;
    for (int i = 0; i < n_in; i++) {
        if (in_sizes[i] == BATCH * DDIM)             i_feats = (const float*)d_in[i];
        else if (in_sizes[i] == BATCH * LTOK * DDIM) img     = (const float*)d_in[i];
        else                                         kptr    = (const int*)d_in[i];
    }
    float* out = (float*)d_out;

    sims_kernel<<<BATCH * (LTOK / TOK_PER_BLOCK), 256>>>(i_feats, img);
    tail_kernel<<<BATCH, 256>>>(img, kptr, out);
}